// round 5
// baseline (speedup 1.0000x reference)
#include <cuda_runtime.h>
#include <cuda_bf16.h>
#include <mma.h>
#include <cstdint>

using namespace nvcuda;

#define B_      32
#define N_      784
#define DIM_    512
#define H_      8
#define KD_     32
#define VD_     128
#define QKV_OUT_ 1536
#define VAL_    1024
#define NT_     (B_*N_)          // 25088
#define EPS_    1e-5f
#define QSCALE_ 0.17677669529663687f   // 1/sqrt(32)
#define LOG2E_  1.4426950408889634f

// ---------------- scratch (device globals; no runtime allocation) ----------
__device__ float g_q[B_*H_*N_*KD_];        // [b][h][n][kd], pre-scaled by QSCALE*log2e
__device__ float g_k[B_*H_*N_*KD_];        // [b][h][n][kd]
__device__ float g_v[B_*H_*N_*VD_];        // [b][h][n][vd]
__device__ float g_bias[H_*N_*N_];         // [h][n][m], pre-scaled by log2e
__device__ float g_o[(size_t)NT_*VAL_];    // hswish(attn out), [b*n][h*VD+vd]
__device__ float g_qw[QKV_OUT_*DIM_];      // qkv_w with BN scale (and q-extra) folded
__device__ float g_pw[DIM_*VAL_];          // proj_w with BN scale folded
__device__ float g_qh[QKV_OUT_];           // BN shift (q-extra folded)
__device__ float g_ph[DIM_];               // BN shift

// ---------------- small helpers --------------------------------------------
__device__ __forceinline__ void cp_async16(void* smem_ptr, const void* gptr){
    uint32_t sa = (uint32_t)__cvta_generic_to_shared(smem_ptr);
    asm volatile("cp.async.ca.shared.global [%0], [%1], 16;\n" :: "r"(sa), "l"(gptr));
}
__device__ __forceinline__ void cp_commit(){ asm volatile("cp.async.commit_group;\n"); }
template<int NN> __device__ __forceinline__ void cp_wait(){ asm volatile("cp.async.wait_group %0;\n" :: "n"(NN)); }

__device__ __forceinline__ void cvt_tf32_a(
    wmma::fragment<wmma::matrix_a,16,16,8,wmma::precision::tf32,wmma::row_major>& f){
#pragma unroll
    for (int i = 0; i < f.num_elements; i++) f.x[i] = wmma::__float_to_tf32(f.x[i]);
}
__device__ __forceinline__ void cvt_tf32_bc(
    wmma::fragment<wmma::matrix_b,16,16,8,wmma::precision::tf32,wmma::col_major>& f){
#pragma unroll
    for (int i = 0; i < f.num_elements; i++) f.x[i] = wmma::__float_to_tf32(f.x[i]);
}
__device__ __forceinline__ void cvt_tf32_br(
    wmma::fragment<wmma::matrix_b,16,16,8,wmma::precision::tf32,wmma::row_major>& f){
#pragma unroll
    for (int i = 0; i < f.num_elements; i++) f.x[i] = wmma::__float_to_tf32(f.x[i]);
}

__device__ __forceinline__ float hswish(float x){
    float t = fminf(fmaxf(x + 3.f, 0.f), 6.f);
    return x * t * (1.f / 6.f);
}

// ---------------- prep: fold BN into weights/shifts + rel-pos bias ---------
__global__ __launch_bounds__(256) void prep_kernel(
    const float* __restrict__ qkv_w,
    const float* __restrict__ qkv_g, const float* __restrict__ qkv_b,
    const float* __restrict__ qkv_m, const float* __restrict__ qkv_v,
    const float* __restrict__ proj_w,
    const float* __restrict__ proj_g, const float* __restrict__ proj_b,
    const float* __restrict__ proj_m, const float* __restrict__ proj_v,
    const float* __restrict__ ab, const int* __restrict__ idxs)
{
    const int gstride = gridDim.x * blockDim.x;
    int tid = blockIdx.x * blockDim.x + threadIdx.x;

    if (tid < QKV_OUT_) {
        float s = qkv_g[tid] * rsqrtf(qkv_v[tid] + EPS_);
        float hshift = qkv_b[tid] - qkv_m[tid] * s;
        int rem = tid % 192;
        if (rem < KD_) hshift *= (QSCALE_ * LOG2E_);
        g_qh[tid] = hshift;
    }
    if (tid < DIM_) {
        float s = proj_g[tid] * rsqrtf(proj_v[tid] + EPS_);
        g_ph[tid] = proj_b[tid] - proj_m[tid] * s;
    }

    // scaled qkv weights (recompute s per element; cheap MUFU)
    for (int i = tid; i < QKV_OUT_*DIM_; i += gstride) {
        int o = i >> 9;                        // /512
        float s = qkv_g[o] * rsqrtf(qkv_v[o] + EPS_);
        int rem = o % 192;
        if (rem < KD_) s *= (QSCALE_ * LOG2E_);
        g_qw[i] = qkv_w[i] * s;
    }
    // scaled proj weights
    for (int i = tid; i < DIM_*VAL_; i += gstride) {
        int o = i >> 10;                       // /1024
        float s = proj_g[o] * rsqrtf(proj_v[o] + EPS_);
        g_pw[i] = proj_w[i] * s;
    }
    // bias[h][n][m] = ab[h][idxs[n][m]] * log2e
    const int total = H_ * N_ * N_;
    for (int i = tid; i < total; i += gstride) {
        int h  = i / (N_ * N_);
        int nm = i - h * (N_ * N_);
        g_bias[i] = ab[h * N_ + idxs[nm]] * LOG2E_;
    }
}

// ---------------- GEMM core pieces -----------------------------------------
#define BK   16
#define LDK  20
#define STG  (128*LDK)            // 2560 floats per stage per matrix
#define LDC2 132
#define HREP 2048                 // 16 x 128 broadcast shift tile
// layout: [0:HREP) hrep | [HREP : HREP+4*STG) stages ; Cs (qkv only) aliases from 0
#define GSM_QKV  (128*LDC2)       // 16896 floats (covers hrep+stages too)
#define GSM_PROJ (HREP + 4*STG)   // 12288
#define GSMEM_QKV_BYTES  (GSM_QKV*4)
#define GSMEM_PROJ_BYTES (GSM_PROJ*4)

extern __shared__ float gsm[];

// mainloop: acc (+= ) A[m0:,:] @ B[n0:,:]^T ; acc pre-initialized by caller.
template<int KDIM>
__device__ __forceinline__ void gemm_mainloop(const float* __restrict__ A,
                                              const float* __restrict__ Bw,
                                              int m0, int n0,
                                              wmma::fragment<wmma::accumulator,16,16,8,float> (&acc)[4][2])
{
    float* As = gsm + HREP;
    float* Bs = As + 2*STG;
    const int tid  = threadIdx.x;
    const int warp = tid >> 5;
    const int warpM = warp >> 2;          // 0..1
    const int warpN = warp & 3;           // 0..3

    const int ar0 = tid >> 1;                    // 0..127
    const int ac0 = (tid & 1) * 8;               // 0 or 8
    const int KT  = KDIM / BK;

    // preload stage 0
    cp_async16(As + ar0*LDK + ac0,     A  + (size_t)(m0+ar0)*KDIM + ac0);
    cp_async16(As + ar0*LDK + ac0 + 4, A  + (size_t)(m0+ar0)*KDIM + ac0 + 4);
    cp_async16(Bs + ar0*LDK + ac0,     Bw + (size_t)(n0+ar0)*KDIM + ac0);
    cp_async16(Bs + ar0*LDK + ac0 + 4, Bw + (size_t)(n0+ar0)*KDIM + ac0 + 4);
    cp_commit();

    for (int kt = 0; kt < KT; kt++) {
        if (kt + 1 < KT) {
            const int stg = (kt+1) & 1;
            const int k0  = (kt+1) * BK;
            cp_async16(As + stg*STG + ar0*LDK + ac0,     A  + (size_t)(m0+ar0)*KDIM + k0 + ac0);
            cp_async16(As + stg*STG + ar0*LDK + ac0 + 4, A  + (size_t)(m0+ar0)*KDIM + k0 + ac0 + 4);
            cp_async16(Bs + stg*STG + ar0*LDK + ac0,     Bw + (size_t)(n0+ar0)*KDIM + k0 + ac0);
            cp_async16(Bs + stg*STG + ar0*LDK + ac0 + 4, Bw + (size_t)(n0+ar0)*KDIM + k0 + ac0 + 4);
            cp_commit();
            cp_wait<1>();
        } else {
            cp_wait<0>();
        }
        __syncthreads();
        const float* Ab = As + (kt&1)*STG;
        const float* Bb = Bs + (kt&1)*STG;
#pragma unroll
        for (int kk = 0; kk < 2; kk++) {
            wmma::fragment<wmma::matrix_a,16,16,8,wmma::precision::tf32,wmma::row_major> af[4];
            wmma::fragment<wmma::matrix_b,16,16,8,wmma::precision::tf32,wmma::col_major> bf[2];
#pragma unroll
            for (int mi=0; mi<4; mi++){
                wmma::load_matrix_sync(af[mi], Ab + (warpM*64 + mi*16)*LDK + kk*8, LDK);
                cvt_tf32_a(af[mi]);
            }
#pragma unroll
            for (int ni=0; ni<2; ni++){
                wmma::load_matrix_sync(bf[ni], Bb + (warpN*32 + ni*16)*LDK + kk*8, LDK);
                cvt_tf32_bc(bf[ni]);
            }
#pragma unroll
            for (int mi=0; mi<4; mi++)
#pragma unroll
                for (int ni=0; ni<2; ni++)
                    wmma::mma_sync(acc[mi][ni], af[mi], bf[ni], acc[mi][ni]);
        }
        __syncthreads();
    }
}

// init acc tiles from broadcast shift vector hvec[n0..n0+127]
__device__ __forceinline__ void acc_init_shift(const float* __restrict__ hvec, int n0,
                                               wmma::fragment<wmma::accumulator,16,16,8,float> (&acc)[4][2])
{
    float* hrep = gsm;                         // [16][128]
    const int tid  = threadIdx.x;
    const int warp = tid >> 5;
    const int warpN = warp & 3;
    for (int i = tid; i < 16*128; i += 256) {
        int c = i & 127;
        hrep[i] = hvec[n0 + c];
    }
    __syncthreads();
#pragma unroll
    for (int mi=0; mi<4; mi++)
#pragma unroll
        for (int ni=0; ni<2; ni++)
            wmma::load_matrix_sync(acc[mi][ni], hrep + warpN*32 + ni*16, 128, wmma::mem_row_major);
    __syncthreads();
}

// ---------------- GEMM1: QKV, scatter to q/k/v -----------------------------
__global__ __launch_bounds__(256) void qkv_gemm(const float* __restrict__ x)
{
    const int m0 = blockIdx.x * 128;
    const int n0 = blockIdx.y * 128;
    wmma::fragment<wmma::accumulator,16,16,8,float> acc[4][2];
    acc_init_shift(g_qh, n0, acc);
    gemm_mainloop<DIM_>(x, g_qw, m0, n0, acc);

    // stage C into smem (aliases hrep+stages; safe after mainloop)
    float* Cs = gsm;
    const int tid  = threadIdx.x;
    const int warp = tid >> 5;
    const int warpM = warp >> 2, warpN = warp & 3;
#pragma unroll
    for (int mi=0; mi<4; mi++)
#pragma unroll
        for (int ni=0; ni<2; ni++)
            wmma::store_matrix_sync(Cs + (warpM*64 + mi*16)*LDC2 + warpN*32 + ni*16,
                                    acc[mi][ni], LDC2, wmma::mem_row_major);
    __syncthreads();

    for (int i = tid; i < 128*128; i += 256) {
        int r = i >> 7, c = i & 127;
        int o = n0 + c;
        float val = Cs[r*LDC2 + c];
        int row = m0 + r;
        int b = row / N_, n = row - b*N_;
        int h = o / 192, rem = o - h*192;
        int base = ((b*H_ + h)*N_ + n);
        if (rem < KD_)            g_q[base*KD_ + rem]                 = val;
        else if (rem < 2*KD_)     g_k[base*KD_ + (rem - KD_)]         = val;
        else                      g_v[(size_t)base*VD_ + (rem - 2*KD_)] = val;
    }
}

// ---------------- GEMM2: out = g_o @ g_pw^T + shift, direct store ----------
__global__ __launch_bounds__(256) void proj_gemm(float* __restrict__ out)
{
    const int m0 = blockIdx.x * 128;
    const int n0 = blockIdx.y * 128;
    wmma::fragment<wmma::accumulator,16,16,8,float> acc[4][2];
    acc_init_shift(g_ph, n0, acc);
    gemm_mainloop<VAL_>(g_o, g_pw, m0, n0, acc);

    const int warp = threadIdx.x >> 5;
    const int warpM = warp >> 2, warpN = warp & 3;
#pragma unroll
    for (int mi=0; mi<4; mi++)
#pragma unroll
        for (int ni=0; ni<2; ni++)
            wmma::store_matrix_sync(out + (size_t)(m0 + warpM*64 + mi*16)*DIM_
                                        + n0 + warpN*32 + ni*16,
                                    acc[mi][ni], DIM_, wmma::mem_row_major);
}

// ---------------- attention: single pass, exp2 fused into fragments --------
// 784 = 7*112. 512 threads (16 warps). block = (b, h, 112-row q tile)
#define QT     112
#define LDQ    36
#define LDV    132
#define LDS_   116
#define ASMEM_FLOATS (QT*LDQ + QT*LDQ + QT*LDV + QT*LDS_ + QT + 448)
#define ASMEM_BYTES  (ASMEM_FLOATS*4)

extern __shared__ float asmem[];

__device__ __forceinline__ void s_tile_exp(int f, const float* Qs, const float* Ks, float* Ss)
{
    int fm = f / 7, fn = f - fm*7;
    wmma::fragment<wmma::accumulator,16,16,8,float> sacc;
    wmma::load_matrix_sync(sacc, Ss + fm*16*LDS_ + fn*16, LDS_, wmma::mem_row_major);
#pragma unroll
    for (int kk = 0; kk < 4; kk++) {
        wmma::fragment<wmma::matrix_a,16,16,8,wmma::precision::tf32,wmma::row_major> af;
        wmma::fragment<wmma::matrix_b,16,16,8,wmma::precision::tf32,wmma::col_major> bf;
        wmma::load_matrix_sync(af, Qs + fm*16*LDQ + kk*8, LDQ);
        cvt_tf32_a(af);
        wmma::load_matrix_sync(bf, Ks + fn*16*LDQ + kk*8, LDQ);
        cvt_tf32_bc(bf);
        wmma::mma_sync(sacc, af, bf, sacc);
    }
#pragma unroll
    for (int i = 0; i < sacc.num_elements; i++) sacc.x[i] = exp2f(sacc.x[i]);
    wmma::store_matrix_sync(Ss + fm*16*LDS_ + fn*16, sacc, LDS_, wmma::mem_row_major);
}

__global__ __launch_bounds__(512) void attn_kernel()
{
    const int qt = blockIdx.x, h = blockIdx.y, b = blockIdx.z;
    const int n0 = qt * QT;
    const int tid = threadIdx.x, warp = tid >> 5;

    float* Qs   = asmem;                  // 112 x 36
    float* Ks   = Qs + QT*LDQ;            // 112 x 36
    float* Vs   = Ks + QT*LDQ;            // 112 x 132 (O staging at end)
    float* Ss   = Vs + QT*LDV;            // 112 x 116 (bias -> P)
    float* Rinv = Ss + QT*LDS_;           // 112
    float* Part = Rinv + QT;              // 448

    const float* qg    = g_q + ((b*H_ + h)*N_ + n0) * KD_;
    const float* kg    = g_k + ((size_t)(b*H_ + h)*N_) * KD_;
    const float* vg    = g_v + ((size_t)(b*H_ + h)*N_) * VD_;
    const float* biasb = g_bias + ((size_t)h*N_ + n0) * N_;   // [112][784]

    // Q tile (112 x 32) — already scaled by QSCALE*log2e
    for (int i = tid; i < QT*8; i += 512) {
        int r = i >> 3, c4 = i & 7;
        *(float4*)&Qs[r*LDQ + c4*4] = *(const float4*)&qg[r*KD_ + c4*4];
    }

    float rsum = 0.f;                                    // owned by tid < 112
    wmma::fragment<wmma::accumulator,16,16,8,float> oacc[4];
#pragma unroll
    for (int i = 0; i < 4; i++) wmma::fill_fragment(oacc[i], 0.f);

    const int strip   = warp & 7;         // O column strip (16 cols)
    const int halfsel = warp >> 3;        // 0 -> fm 0..3, 1 -> fm 4..6
    const int fm0     = halfsel * 4;
    const int fmN     = halfsel ? 3 : 4;

    for (int mt = 0; mt < 7; mt++) {
        const int m0 = mt * QT;
        __syncthreads();   // protects Ks/Vs/Ss/Part from previous iteration readers/writers
        if (mt > 0 && tid < QT)
            rsum += Part[4*tid] + Part[4*tid+1] + Part[4*tid+2] + Part[4*tid+3];

        // K (112x32), V (112x128), bias -> Ss (112x112)
        for (int i = tid; i < QT*8; i += 512) {
            int r = i >> 3, c4 = i & 7;
            *(float4*)&Ks[r*LDQ + c4*4] = *(const float4*)&kg[(size_t)(m0 + r)*KD_ + c4*4];
        }
        for (int i = tid; i < QT*32; i += 512) {
            int r = i >> 5, c4 = i & 31;
            *(float4*)&Vs[r*LDV + c4*4] = *(const float4*)&vg[(size_t)(m0 + r)*VD_ + c4*4];
        }
        for (int i = tid; i < QT*28; i += 512) {
            int r = i / 28, c4 = i - r*28;
            *(float4*)&Ss[r*LDS_ + c4*4] = *(const float4*)&biasb[(size_t)r*N_ + m0 + c4*4];
        }
        __syncthreads();

        // P = exp2(bias + Q @ K^T)  — exp2 applied on accumulator registers.
        // 49 tiles: warps get f = warp, warp+16, warp+32; tile 48 goes to warp 15
        // (which is in the lighter 3-fm P@V group).
        for (int f = warp; f < 48; f += 16) s_tile_exp(f, Qs, Ks, Ss);
        if (warp == 15)                     s_tile_exp(48, Qs, Ks, Ss);
        __syncthreads();

        // O += P @ V   (kk outer: load V fragment once per kk)
#pragma unroll
        for (int kk = 0; kk < 14; kk++) {
            wmma::fragment<wmma::matrix_b,16,16,8,wmma::precision::tf32,wmma::row_major> bf;
            wmma::load_matrix_sync(bf, Vs + kk*8*LDV + strip*16, LDV);
            cvt_tf32_br(bf);
#pragma unroll
            for (int fi = 0; fi < 4; fi++) {
                if (fi >= fmN) break;
                wmma::fragment<wmma::matrix_a,16,16,8,wmma::precision::tf32,wmma::row_major> af;
                wmma::load_matrix_sync(af, Ss + (fm0 + fi)*16*LDS_ + kk*8, LDS_);
                cvt_tf32_a(af);
                wmma::mma_sync(oacc[fi], af, bf, oacc[fi]);
            }
        }

        // row-sum partials (4 threads per row) — reads P, no extra sync needed
        if (tid < 448) {
            int r = tid >> 2, q = tid & 3;
            const float* row = Ss + r*LDS_ + q*28;
            float s = 0.f;
#pragma unroll
            for (int j = 0; j < 28; j++) s += row[j];
            Part[tid] = s;
        }
    }

    __syncthreads();
    if (tid < QT) {
        rsum += Part[4*tid] + Part[4*tid+1] + Part[4*tid+2] + Part[4*tid+3];
        Rinv[tid] = 1.f / rsum;
    }
    __syncthreads();                     // all P@V done -> Vs reusable; Rinv ready

    // stage O into Vs, then normalize + hswish + write
#pragma unroll
    for (int fi = 0; fi < 4; fi++) {
        if (fi >= fmN) break;
        wmma::store_matrix_sync(Vs + (fm0 + fi)*16*LDV + strip*16, oacc[fi],
                                LDV, wmma::mem_row_major);
    }
    __syncthreads();

    float* og = g_o + ((size_t)(b*N_ + n0))*VAL_ + h*VD_;
    for (int i = tid; i < QT*VD_; i += 512) {
        int r = i >> 7, c = i & 127;
        float v = Vs[r*LDV + c] * Rinv[r];
        og[(size_t)r*VAL_ + c] = hswish(v);
    }
}

// ---------------- launch ---------------------------------------------------
extern "C" void kernel_launch(void* const* d_in, const int* in_sizes, int n_in,
                              void* d_out, int out_size)
{
    const float* x      = (const float*)d_in[0];
    const float* qkv_w  = (const float*)d_in[1];
    const float* qkv_g  = (const float*)d_in[2];
    const float* qkv_b  = (const float*)d_in[3];
    const float* qkv_m  = (const float*)d_in[4];
    const float* qkv_v  = (const float*)d_in[5];
    const float* ab     = (const float*)d_in[6];
    const float* proj_w = (const float*)d_in[7];
    const float* proj_g = (const float*)d_in[8];
    const float* proj_b = (const float*)d_in[9];
    const float* proj_m = (const float*)d_in[10];
    const float* proj_v = (const float*)d_in[11];
    const int*   idxs   = (const int*)d_in[12];
    float*       out    = (float*)d_out;

    cudaFuncSetAttribute(attn_kernel, cudaFuncAttributeMaxDynamicSharedMemorySize, ASMEM_BYTES);
    cudaFuncSetAttribute(qkv_gemm,   cudaFuncAttributeMaxDynamicSharedMemorySize, GSMEM_QKV_BYTES);
    cudaFuncSetAttribute(proj_gemm,  cudaFuncAttributeMaxDynamicSharedMemorySize, GSMEM_PROJ_BYTES);

    prep_kernel<<<4096, 256>>>(qkv_w, qkv_g, qkv_b, qkv_m, qkv_v,
                               proj_w, proj_g, proj_b, proj_m, proj_v, ab, idxs);

    dim3 g1(NT_/128, QKV_OUT_/128);            // 196 x 12
    qkv_gemm<<<g1, 256, GSMEM_QKV_BYTES>>>(x);

    dim3 ga(7, H_, B_);                        // 7 x 8 x 32
    attn_kernel<<<ga, 512, ASMEM_BYTES>>>();

    dim3 g2(NT_/128, DIM_/128);                // 196 x 4
    proj_gemm<<<g2, 256, GSMEM_PROJ_BYTES>>>(out);
}

// round 7
// speedup vs baseline: 1.1678x; 1.1678x over previous
#include <cuda_runtime.h>
#include <cuda_bf16.h>
#include <mma.h>
#include <cstdint>

using namespace nvcuda;

#define B_      32
#define N_      784
#define DIM_    512
#define H_      8
#define KD_     32
#define VD_     128
#define QKV_OUT_ 1536
#define VAL_    1024
#define NT_     (B_*N_)          // 25088
#define EPS_    1e-5f
#define QSCALE_ 0.17677669529663687f   // 1/sqrt(32)
#define LOG2E_  1.4426950408889634f

// ---------------- scratch (device globals; no runtime allocation) ----------
__device__ float g_q[B_*H_*N_*KD_];        // [b][h][n][kd], pre-scaled by QSCALE*log2e
__device__ float g_k[B_*H_*N_*KD_];        // [b][h][n][kd]
__device__ float g_v[B_*H_*N_*VD_];        // [b][h][n][vd]
__device__ float g_bias[H_*N_*N_];         // [h][n][m], pre-scaled by log2e
__device__ float g_o[(size_t)NT_*VAL_];    // hswish(attn out), [b*n][h*VD+vd]
__device__ float g_qw[QKV_OUT_*DIM_];      // qkv_w with BN scale (and q-extra) folded
__device__ float g_pw[DIM_*VAL_];          // proj_w with BN scale folded
__device__ float g_qh[QKV_OUT_];           // BN shift (q-extra folded)
__device__ float g_ph[DIM_];               // BN shift

// ---------------- small helpers --------------------------------------------
__device__ __forceinline__ void cp_async16(void* smem_ptr, const void* gptr){
    uint32_t sa = (uint32_t)__cvta_generic_to_shared(smem_ptr);
    asm volatile("cp.async.ca.shared.global [%0], [%1], 16;\n" :: "r"(sa), "l"(gptr));
}
__device__ __forceinline__ void cp_commit(){ asm volatile("cp.async.commit_group;\n"); }
template<int NN> __device__ __forceinline__ void cp_wait(){ asm volatile("cp.async.wait_group %0;\n" :: "n"(NN)); }

__device__ __forceinline__ void cvt_tf32_a(
    wmma::fragment<wmma::matrix_a,16,16,8,wmma::precision::tf32,wmma::row_major>& f){
#pragma unroll
    for (int i = 0; i < f.num_elements; i++) f.x[i] = wmma::__float_to_tf32(f.x[i]);
}
__device__ __forceinline__ void cvt_tf32_bc(
    wmma::fragment<wmma::matrix_b,16,16,8,wmma::precision::tf32,wmma::col_major>& f){
#pragma unroll
    for (int i = 0; i < f.num_elements; i++) f.x[i] = wmma::__float_to_tf32(f.x[i]);
}
__device__ __forceinline__ void cvt_tf32_br(
    wmma::fragment<wmma::matrix_b,16,16,8,wmma::precision::tf32,wmma::row_major>& f){
#pragma unroll
    for (int i = 0; i < f.num_elements; i++) f.x[i] = wmma::__float_to_tf32(f.x[i]);
}

__device__ __forceinline__ float hswish(float x){
    float t = fminf(fmaxf(x + 3.f, 0.f), 6.f);
    return x * t * (1.f / 6.f);
}

// ---------------- prep: fold BN into weights/shifts + rel-pos bias ---------
__global__ __launch_bounds__(256) void prep_kernel(
    const float* __restrict__ qkv_w,
    const float* __restrict__ qkv_g, const float* __restrict__ qkv_b,
    const float* __restrict__ qkv_m, const float* __restrict__ qkv_v,
    const float* __restrict__ proj_w,
    const float* __restrict__ proj_g, const float* __restrict__ proj_b,
    const float* __restrict__ proj_m, const float* __restrict__ proj_v,
    const float* __restrict__ ab, const int* __restrict__ idxs)
{
    const int gstride = gridDim.x * blockDim.x;
    int tid = blockIdx.x * blockDim.x + threadIdx.x;

    if (tid < QKV_OUT_) {
        float s = qkv_g[tid] * rsqrtf(qkv_v[tid] + EPS_);
        float hshift = qkv_b[tid] - qkv_m[tid] * s;
        int rem = tid % 192;
        if (rem < KD_) hshift *= (QSCALE_ * LOG2E_);
        g_qh[tid] = hshift;
    }
    if (tid < DIM_) {
        float s = proj_g[tid] * rsqrtf(proj_v[tid] + EPS_);
        g_ph[tid] = proj_b[tid] - proj_m[tid] * s;
    }

    for (int i = tid; i < QKV_OUT_*DIM_; i += gstride) {
        int o = i >> 9;                        // /512
        float s = qkv_g[o] * rsqrtf(qkv_v[o] + EPS_);
        int rem = o % 192;
        if (rem < KD_) s *= (QSCALE_ * LOG2E_);
        g_qw[i] = qkv_w[i] * s;
    }
    for (int i = tid; i < DIM_*VAL_; i += gstride) {
        int o = i >> 10;                       // /1024
        float s = proj_g[o] * rsqrtf(proj_v[o] + EPS_);
        g_pw[i] = proj_w[i] * s;
    }
    const int total = H_ * N_ * N_;
    for (int i = tid; i < total; i += gstride) {
        int h  = i / (N_ * N_);
        int nm = i - h * (N_ * N_);
        g_bias[i] = ab[h * N_ + idxs[nm]] * LOG2E_;
    }
}

// ---------------- GEMM core pieces (BK=32, double-buffered cp.async) -------
#define BK2  32
#define LDK2 36
#define STG2 (128*LDK2)           // 4608 floats per stage per matrix
#define LDC2 132
#define HREP 2048                 // 16 x 128 broadcast shift tile
#define GSM_FLOATS (HREP + 4*STG2)   // 20480 floats (also covers Cs 128x132=16896)
#define GSMEM_BYTES (GSM_FLOATS*4)

extern __shared__ float gsm[];

template<int KDIM>
__device__ __forceinline__ void gemm_mainloop(const float* __restrict__ A,
                                              const float* __restrict__ Bw,
                                              int m0, int n0,
                                              wmma::fragment<wmma::accumulator,16,16,8,float> (&acc)[4][2])
{
    float* As = gsm + HREP;
    float* Bs = As + 2*STG2;
    const int tid  = threadIdx.x;
    const int warp = tid >> 5;
    const int warpM = warp >> 2;          // 0..1
    const int warpN = warp & 3;           // 0..3

    const int ar0 = tid >> 1;                    // 0..127
    const int ac0 = (tid & 1) * 16;              // 0 or 16
    const int KT  = KDIM / BK2;

    // preload stage 0
#pragma unroll
    for (int q = 0; q < 4; q++) {
        cp_async16(As + ar0*LDK2 + ac0 + q*4, A  + (size_t)(m0+ar0)*KDIM + ac0 + q*4);
        cp_async16(Bs + ar0*LDK2 + ac0 + q*4, Bw + (size_t)(n0+ar0)*KDIM + ac0 + q*4);
    }
    cp_commit();

    for (int kt = 0; kt < KT; kt++) {
        if (kt + 1 < KT) {
            const int stg = (kt+1) & 1;
            const int k0  = (kt+1) * BK2;
#pragma unroll
            for (int q = 0; q < 4; q++) {
                cp_async16(As + stg*STG2 + ar0*LDK2 + ac0 + q*4, A  + (size_t)(m0+ar0)*KDIM + k0 + ac0 + q*4);
                cp_async16(Bs + stg*STG2 + ar0*LDK2 + ac0 + q*4, Bw + (size_t)(n0+ar0)*KDIM + k0 + ac0 + q*4);
            }
            cp_commit();
            cp_wait<1>();
        } else {
            cp_wait<0>();
        }
        __syncthreads();
        const float* Ab = As + (kt&1)*STG2;
        const float* Bb = Bs + (kt&1)*STG2;
#pragma unroll
        for (int kk = 0; kk < 4; kk++) {
            wmma::fragment<wmma::matrix_a,16,16,8,wmma::precision::tf32,wmma::row_major> af[4];
            wmma::fragment<wmma::matrix_b,16,16,8,wmma::precision::tf32,wmma::col_major> bf[2];
#pragma unroll
            for (int mi=0; mi<4; mi++){
                wmma::load_matrix_sync(af[mi], Ab + (warpM*64 + mi*16)*LDK2 + kk*8, LDK2);
                cvt_tf32_a(af[mi]);
            }
#pragma unroll
            for (int ni=0; ni<2; ni++){
                wmma::load_matrix_sync(bf[ni], Bb + (warpN*32 + ni*16)*LDK2 + kk*8, LDK2);
                cvt_tf32_bc(bf[ni]);
            }
#pragma unroll
            for (int mi=0; mi<4; mi++)
#pragma unroll
                for (int ni=0; ni<2; ni++)
                    wmma::mma_sync(acc[mi][ni], af[mi], bf[ni], acc[mi][ni]);
        }
        __syncthreads();
    }
}

__device__ __forceinline__ void acc_init_shift(const float* __restrict__ hvec, int n0,
                                               wmma::fragment<wmma::accumulator,16,16,8,float> (&acc)[4][2])
{
    float* hrep = gsm;                         // [16][128]
    const int tid  = threadIdx.x;
    const int warp = tid >> 5;
    const int warpN = warp & 3;
    for (int i = tid; i < 16*128; i += 256) {
        int c = i & 127;
        hrep[i] = hvec[n0 + c];
    }
    __syncthreads();
#pragma unroll
    for (int mi=0; mi<4; mi++)
#pragma unroll
        for (int ni=0; ni<2; ni++)
            wmma::load_matrix_sync(acc[mi][ni], hrep + warpN*32 + ni*16, 128, wmma::mem_row_major);
    __syncthreads();
}

// ---------------- GEMM1: QKV, scatter to q/k/v -----------------------------
__global__ __launch_bounds__(256) void qkv_gemm(const float* __restrict__ x)
{
    const int m0 = blockIdx.x * 128;
    const int n0 = blockIdx.y * 128;
    wmma::fragment<wmma::accumulator,16,16,8,float> acc[4][2];
    acc_init_shift(g_qh, n0, acc);
    gemm_mainloop<DIM_>(x, g_qw, m0, n0, acc);

    float* Cs = gsm;
    const int tid  = threadIdx.x;
    const int warp = tid >> 5;
    const int warpM = warp >> 2, warpN = warp & 3;
#pragma unroll
    for (int mi=0; mi<4; mi++)
#pragma unroll
        for (int ni=0; ni<2; ni++)
            wmma::store_matrix_sync(Cs + (warpM*64 + mi*16)*LDC2 + warpN*32 + ni*16,
                                    acc[mi][ni], LDC2, wmma::mem_row_major);
    __syncthreads();

    for (int i = tid; i < 128*128; i += 256) {
        int r = i >> 7, c = i & 127;
        int o = n0 + c;
        float val = Cs[r*LDC2 + c];
        int row = m0 + r;
        int b = row / N_, n = row - b*N_;
        int h = o / 192, rem = o - h*192;
        int base = ((b*H_ + h)*N_ + n);
        if (rem < KD_)            g_q[base*KD_ + rem]                 = val;
        else if (rem < 2*KD_)     g_k[base*KD_ + (rem - KD_)]         = val;
        else                      g_v[(size_t)base*VD_ + (rem - 2*KD_)] = val;
    }
}

// ---------------- GEMM2: out = g_o @ g_pw^T + shift, direct store ----------
__global__ __launch_bounds__(256) void proj_gemm(float* __restrict__ out)
{
    const int m0 = blockIdx.x * 128;
    const int n0 = blockIdx.y * 128;
    wmma::fragment<wmma::accumulator,16,16,8,float> acc[4][2];
    acc_init_shift(g_ph, n0, acc);
    gemm_mainloop<VAL_>(g_o, g_pw, m0, n0, acc);

    const int warp = threadIdx.x >> 5;
    const int warpM = warp >> 2, warpN = warp & 3;
#pragma unroll
    for (int mi=0; mi<4; mi++)
#pragma unroll
        for (int ni=0; ni<2; ni++)
            wmma::store_matrix_sync(out + (size_t)(m0 + warpM*64 + mi*16)*DIM_
                                        + n0 + warpN*32 + ni*16,
                                    acc[mi][ni], DIM_, wmma::mem_row_major);
}

// ---------------- attention: cp.async K/V pipeline, bias acc-init ----------
// 784 = 7*112. 512 threads (16 warps). block = (b, h, 112-row q tile)
#define QT     112
#define LDQ    36
#define LDV    132
#define LDS_   116
#define KSTG   (QT*LDQ)           // 4032
#define VSTG   (QT*LDV)           // 14784
// layout: Qs | Ks[2] | Vs[2] | Ss | Rinv | Part
#define AOFF_K   (QT*LDQ)
#define AOFF_V   (AOFF_K + 2*KSTG)
#define AOFF_S   (AOFF_V + 2*VSTG)
#define AOFF_RI  (AOFF_S + QT*LDS_)
#define AOFF_PT  (AOFF_RI + QT)
#define ASMEM_FLOATS (AOFF_PT + 448)
#define ASMEM_BYTES  (ASMEM_FLOATS*4)

extern __shared__ float asmem[];

__device__ __forceinline__ void s_tile_exp(int f, const float* Qs, const float* Ks, float* Ss,
                                           const float* __restrict__ biasb, int m0)
{
    int fm = f / 7, fn = f - fm*7;
    wmma::fragment<wmma::accumulator,16,16,8,float> sacc;
    // bias accumulator init straight from global (L2-resident, ldm=784)
    wmma::load_matrix_sync(sacc, biasb + (size_t)fm*16*N_ + m0 + fn*16, N_, wmma::mem_row_major);
#pragma unroll
    for (int kk = 0; kk < 4; kk++) {
        wmma::fragment<wmma::matrix_a,16,16,8,wmma::precision::tf32,wmma::row_major> af;
        wmma::fragment<wmma::matrix_b,16,16,8,wmma::precision::tf32,wmma::col_major> bf;
        wmma::load_matrix_sync(af, Qs + fm*16*LDQ + kk*8, LDQ);
        cvt_tf32_a(af);
        wmma::load_matrix_sync(bf, Ks + fn*16*LDQ + kk*8, LDQ);
        cvt_tf32_bc(bf);
        wmma::mma_sync(sacc, af, bf, sacc);
    }
#pragma unroll
    for (int i = 0; i < sacc.num_elements; i++) sacc.x[i] = exp2f(sacc.x[i]);
    wmma::store_matrix_sync(Ss + fm*16*LDS_ + fn*16, sacc, LDS_, wmma::mem_row_major);
}

__global__ __launch_bounds__(512) void attn_kernel()
{
    const int qt = blockIdx.x, h = blockIdx.y, b = blockIdx.z;
    const int n0 = qt * QT;
    const int tid = threadIdx.x, warp = tid >> 5;

    float* Qs   = asmem;
    float* Ks   = asmem + AOFF_K;         // 2 stages of 112x36
    float* Vs   = asmem + AOFF_V;         // 2 stages of 112x132
    float* Ss   = asmem + AOFF_S;         // 112x116 (P)
    float* Rinv = asmem + AOFF_RI;        // 112
    float* Part = asmem + AOFF_PT;        // 448

    const float* qg    = g_q + ((b*H_ + h)*N_ + n0) * KD_;
    const float* kg    = g_k + ((size_t)(b*H_ + h)*N_) * KD_;
    const float* vg    = g_v + ((size_t)(b*H_ + h)*N_) * VD_;
    const float* biasb = g_bias + ((size_t)h*N_ + n0) * N_;   // [112][784]

    // Q tile (112 x 32) — plain loads; barrier at top of iter 0 covers it
    for (int i = tid; i < QT*8; i += 512) {
        int r = i >> 3, c4 = i & 7;
        *(float4*)&Qs[r*LDQ + c4*4] = *(const float4*)&qg[r*KD_ + c4*4];
    }

    // prologue: prefetch mt=0 into stage 0
    {
        for (int i = tid; i < QT*8; i += 512) {          // K
            int r = i >> 3, c = (i & 7)*4;
            cp_async16(Ks + r*LDQ + c, kg + (size_t)r*KD_ + c);
        }
        for (int i = tid; i < QT*32; i += 512) {         // V
            int r = i >> 5, c = (i & 31)*4;
            cp_async16(Vs + r*LDV + c, vg + (size_t)r*VD_ + c);
        }
        cp_commit();
    }

    float rsum = 0.f;                                    // owned by tid < 112
    wmma::fragment<wmma::accumulator,16,16,8,float> oacc[4];
#pragma unroll
    for (int i = 0; i < 4; i++) wmma::fill_fragment(oacc[i], 0.f);

    const int strip   = warp & 7;         // O column strip (16 cols)
    const int halfsel = warp >> 3;        // 0 -> fm 0..3, 1 -> fm 4..6
    const int fm0     = halfsel * 4;
    const int fmN     = halfsel ? 3 : 4;

    for (int mt = 0; mt < 7; mt++) {
        const int cur = mt & 1;
        // stage cur was committed in iter mt-1 (or prologue) and has had a full
        // iteration of compute to land; wait own groups, then barrier for
        // cross-thread visibility. Barrier also separates iter mt-1 reads of
        // stage cur^1 / Ss / Part from this iteration's writes.
        cp_wait<0>();
        __syncthreads();

        if (mt > 0 && tid < QT)
            rsum += Part[4*tid] + Part[4*tid+1] + Part[4*tid+2] + Part[4*tid+3];

        // prefetch mt+1 into stage cur^1 (overlaps with this iter's compute)
        if (mt + 1 < 7) {
            const int m1 = (mt+1) * QT;
            float* Kn = Ks + (cur^1)*KSTG;
            float* Vn = Vs + (cur^1)*VSTG;
            for (int i = tid; i < QT*8; i += 512) {
                int r = i >> 3, c = (i & 7)*4;
                cp_async16(Kn + r*LDQ + c, kg + (size_t)(m1 + r)*KD_ + c);
            }
            for (int i = tid; i < QT*32; i += 512) {
                int r = i >> 5, c = (i & 31)*4;
                cp_async16(Vn + r*LDV + c, vg + (size_t)(m1 + r)*VD_ + c);
            }
            cp_commit();
        }

        const int m0 = mt * QT;
        const float* Kc = Ks + cur*KSTG;
        const float* Vc = Vs + cur*VSTG;

        // P = exp2(bias + Q @ K^T)
        for (int f = warp; f < 48; f += 16) s_tile_exp(f, Qs, Kc, Ss, biasb, m0);
        if (warp == 15)                     s_tile_exp(48, Qs, Kc, Ss, biasb, m0);
        __syncthreads();

        // O += P @ V   (kk outer: V fragment loaded once per kk)
#pragma unroll
        for (int kk = 0; kk < 14; kk++) {
            wmma::fragment<wmma::matrix_b,16,16,8,wmma::precision::tf32,wmma::row_major> bf;
            wmma::load_matrix_sync(bf, Vc + kk*8*LDV + strip*16, LDV);
            cvt_tf32_br(bf);
#pragma unroll
            for (int fi = 0; fi < 4; fi++) {
                if (fi >= fmN) break;
                wmma::fragment<wmma::matrix_a,16,16,8,wmma::precision::tf32,wmma::row_major> af;
                wmma::load_matrix_sync(af, Ss + (fm0 + fi)*16*LDS_ + kk*8, LDS_);
                cvt_tf32_a(af);
                wmma::mma_sync(oacc[fi], af, bf, oacc[fi]);
            }
        }

        // row-sum partials (4 threads per row); read at next top barrier
        if (tid < 448) {
            int r = tid >> 2, q = tid & 3;
            const float* row = Ss + r*LDS_ + q*28;
            float s = 0.f;
#pragma unroll
            for (int j = 0; j < 28; j++) s += row[j];
            Part[tid] = s;
        }
    }

    __syncthreads();
    if (tid < QT) {
        rsum += Part[4*tid] + Part[4*tid+1] + Part[4*tid+2] + Part[4*tid+3];
        Rinv[tid] = 1.f / rsum;
    }
    __syncthreads();                     // all P@V done -> Vs reusable; Rinv ready

    // stage O into Vs (stage 0), then normalize + hswish + write
#pragma unroll
    for (int fi = 0; fi < 4; fi++) {
        if (fi >= fmN) break;
        wmma::store_matrix_sync(Vs + (fm0 + fi)*16*LDV + strip*16, oacc[fi],
                                LDV, wmma::mem_row_major);
    }
    __syncthreads();

    float* og = g_o + ((size_t)(b*N_ + n0))*VAL_ + h*VD_;
    for (int i = tid; i < QT*VD_; i += 512) {
        int r = i >> 7, c = i & 127;
        float v = Vs[r*LDV + c] * Rinv[r];
        og[(size_t)r*VAL_ + c] = hswish(v);
    }
}

// ---------------- launch ---------------------------------------------------
extern "C" void kernel_launch(void* const* d_in, const int* in_sizes, int n_in,
                              void* d_out, int out_size)
{
    const float* x      = (const float*)d_in[0];
    const float* qkv_w  = (const float*)d_in[1];
    const float* qkv_g  = (const float*)d_in[2];
    const float* qkv_b  = (const float*)d_in[3];
    const float* qkv_m  = (const float*)d_in[4];
    const float* qkv_v  = (const float*)d_in[5];
    const float* ab     = (const float*)d_in[6];
    const float* proj_w = (const float*)d_in[7];
    const float* proj_g = (const float*)d_in[8];
    const float* proj_b = (const float*)d_in[9];
    const float* proj_m = (const float*)d_in[10];
    const float* proj_v = (const float*)d_in[11];
    const int*   idxs   = (const int*)d_in[12];
    float*       out    = (float*)d_out;

    cudaFuncSetAttribute(attn_kernel, cudaFuncAttributeMaxDynamicSharedMemorySize, ASMEM_BYTES);
    cudaFuncSetAttribute(qkv_gemm,   cudaFuncAttributeMaxDynamicSharedMemorySize, GSMEM_BYTES);
    cudaFuncSetAttribute(proj_gemm,  cudaFuncAttributeMaxDynamicSharedMemorySize, GSMEM_BYTES);

    prep_kernel<<<4096, 256>>>(qkv_w, qkv_g, qkv_b, qkv_m, qkv_v,
                               proj_w, proj_g, proj_b, proj_m, proj_v, ab, idxs);

    dim3 g1(NT_/128, QKV_OUT_/128);            // 196 x 12
    qkv_gemm<<<g1, 256, GSMEM_BYTES>>>(x);

    dim3 ga(7, H_, B_);                        // 7 x 8 x 32
    attn_kernel<<<ga, 512, ASMEM_BYTES>>>();

    dim3 g2(NT_/128, DIM_/128);                // 196 x 4
    proj_gemm<<<g2, 256, GSMEM_BYTES>>>(out);
}